// round 11
// baseline (speedup 1.0000x reference)
#include <cuda_runtime.h>
#include <cuda_bf16.h>
#include <cstdint>

// ---------------- problem constants ----------------
#define N_NODES 50000
#define N_EDGES 800000
#define IN_C    128
#define HID_C   16
#define HEADS   8
#define H1      (HEADS * HID_C)   // 128
#define OUT_C   64
#define NEG_SLOPE 0.2f

// ---------------- scratch (device globals; no allocation allowed) ----------------
__device__ float g_xh1[(size_t)N_NODES * H1];     // layer1 linear output  [N,128]
__device__ float g_asrc1[(size_t)N_NODES * HEADS];
__device__ float g_adst1[(size_t)N_NODES * HEADS];
__device__ float g_denom1[(size_t)N_NODES * HEADS];
__device__ float g_acc1[(size_t)N_NODES * H1];    // layer1 aggregation + h (after ELU)
__device__ float g_xh2[(size_t)N_NODES * OUT_C];  // layer2 linear output  [N,64]
__device__ float g_asrc2[N_NODES];
__device__ float g_adst2[N_NODES];
__device__ float g_denom2[N_NODES];
__device__ int   g_src[N_EDGES];
__device__ int   g_dst[N_EDGES];
__device__ int   g_is64;

// ---------------- helpers ----------------
__device__ __forceinline__ float lrelu(float x) { return x > 0.f ? x : NEG_SLOPE * x; }

// ---------------- edge dtype detection + canonicalization ----------------
// int64 data (values < 50000, little-endian) => odd 32-bit slots are all zero.
// int32 data => odd slots are random node indices (never all zero over 64K).
__global__ void detect_kernel(const unsigned int* __restrict__ ei32) {
    __shared__ unsigned int sv[256];
    int tid = threadIdx.x;
    unsigned int v = 0;
    for (int i = tid; i < 65536; i += 256) v |= ei32[2 * i + 1];
    sv[tid] = v;
    __syncthreads();
    for (int s = 128; s > 0; s >>= 1) {
        if (tid < s) sv[tid] |= sv[tid + s];
        __syncthreads();
    }
    if (tid == 0) g_is64 = (sv[0] == 0u) ? 1 : 0;
}

__global__ void convert_kernel(const int* __restrict__ ei) {
    int e = blockIdx.x * blockDim.x + threadIdx.x;
    if (e >= N_EDGES) return;
    int s, d;
    if (g_is64) {
        const long long* p = (const long long*)ei;
        s = (int)p[e];
        d = (int)p[N_EDGES + e];
    } else {
        s = ei[e];
        d = ei[e + N_EDGES];
    }
    g_src[e] = s;
    g_dst[e] = d;
}

// ---------------- zero kernels ----------------
__global__ void zero_acc1_kernel() {
    int gid = blockIdx.x * blockDim.x + threadIdx.x;
    if (gid < N_NODES * (H1 / 4)) {
        reinterpret_cast<float4*>(g_acc1)[gid] = make_float4(0.f, 0.f, 0.f, 0.f);
    }
}
__global__ void zero_out_kernel(float* __restrict__ out) {
    int gid = blockIdx.x * blockDim.x + threadIdx.x;
    if (gid < N_NODES * (OUT_C / 4)) {
        reinterpret_cast<float4*>(out)[gid] = make_float4(0.f, 0.f, 0.f, 0.f);
    }
}

// ---------------- tiled GEMM: C[M,N] = A[M,128] * B[128,N] ----------------
template <int N, int TN>
__global__ void gemm_kernel(const float* __restrict__ A, const float* __restrict__ B,
                            float* __restrict__ C, int M) {
    constexpr int K  = 128;
    constexpr int BM = 64;
    constexpr int BK = 16;
    __shared__ float As[BK][BM + 4];
    __shared__ float Bs[BK][N];

    int tid = threadIdx.x;
    int tx = tid & 15;
    int ty = tid >> 4;
    int m0 = blockIdx.x * BM;

    float acc[4][TN];
#pragma unroll
    for (int r = 0; r < 4; r++)
#pragma unroll
        for (int c = 0; c < TN; c++) acc[r][c] = 0.f;

    int arow = tid >> 2;
    int akk  = (tid & 3) * 4;

    for (int kt = 0; kt < K; kt += BK) {
        float4 a4 = make_float4(0.f, 0.f, 0.f, 0.f);
        int gr = m0 + arow;
        if (gr < M)
            a4 = *reinterpret_cast<const float4*>(A + (size_t)gr * K + kt + akk);
        As[akk + 0][arow] = a4.x;
        As[akk + 1][arow] = a4.y;
        As[akk + 2][arow] = a4.z;
        As[akk + 3][arow] = a4.w;

        constexpr int NF4 = BK * N / 4;
#pragma unroll
        for (int i = 0; i < NF4 / 256; i++) {
            int idx = tid + i * 256;
            int br = idx / (N / 4);
            int bc = idx % (N / 4);
            float4 b4 = *reinterpret_cast<const float4*>(B + (size_t)(kt + br) * N + bc * 4);
            *reinterpret_cast<float4*>(&Bs[br][bc * 4]) = b4;
        }
        __syncthreads();

#pragma unroll
        for (int k = 0; k < BK; k++) {
            float a[4];
#pragma unroll
            for (int r = 0; r < 4; r++) a[r] = As[k][ty * 4 + r];
            float b[TN];
#pragma unroll
            for (int c = 0; c < TN; c++) b[c] = Bs[k][tx * TN + c];
#pragma unroll
            for (int r = 0; r < 4; r++)
#pragma unroll
                for (int c = 0; c < TN; c++) acc[r][c] += a[r] * b[c];
        }
        __syncthreads();
    }

#pragma unroll
    for (int r = 0; r < 4; r++) {
        int gr = m0 + ty * 4 + r;
        if (gr < M) {
#pragma unroll
            for (int c = 0; c < TN; c += 4) {
                float4 v = make_float4(acc[r][c], acc[r][c + 1], acc[r][c + 2], acc[r][c + 3]);
                *reinterpret_cast<float4*>(C + (size_t)gr * N + tx * TN + c) = v;
            }
        }
    }
}

// ---------------- layer 1 attention coefficients (warp per node) ----------------
__global__ void attn1_kernel(const float* __restrict__ att_src,
                             const float* __restrict__ att_dst) {
    int gw   = (blockIdx.x * blockDim.x + threadIdx.x) >> 5;
    int lane = threadIdx.x & 31;
    if (gw >= N_NODES) return;
    float4 xv = *reinterpret_cast<const float4*>(g_xh1 + (size_t)gw * H1 + lane * 4);
    float4 as = *reinterpret_cast<const float4*>(att_src + lane * 4);
    float4 ad = *reinterpret_cast<const float4*>(att_dst + lane * 4);
    float ps = xv.x * as.x + xv.y * as.y + xv.z * as.z + xv.w * as.w;
    float pd = xv.x * ad.x + xv.y * ad.y + xv.z * ad.z + xv.w * ad.w;
    ps += __shfl_xor_sync(0xffffffffu, ps, 1);
    ps += __shfl_xor_sync(0xffffffffu, ps, 2);
    pd += __shfl_xor_sync(0xffffffffu, pd, 1);
    pd += __shfl_xor_sync(0xffffffffu, pd, 2);
    if ((lane & 3) == 0) {
        int h = lane >> 2;
        g_asrc1[(size_t)gw * HEADS + h] = ps;
        g_adst1[(size_t)gw * HEADS + h] = pd;
        g_denom1[(size_t)gw * HEADS + h] = __expf(lrelu(ps + pd));  // self-loop seed
    }
}

// ---------------- layer 1 edge pass A: softmax denominators ----------------
__global__ void edge1_denom_kernel() {
    int e = blockIdx.x * blockDim.x + threadIdx.x;
    if (e >= N_EDGES) return;
    int s = g_src[e], d = g_dst[e];
    const float4* ap = reinterpret_cast<const float4*>(g_asrc1 + (size_t)s * HEADS);
    const float4* bp = reinterpret_cast<const float4*>(g_adst1 + (size_t)d * HEADS);
    float4 a0 = __ldg(ap), a1 = __ldg(ap + 1);
    float4 b0 = __ldg(bp), b1 = __ldg(bp + 1);
    float4 e0 = make_float4(__expf(lrelu(a0.x + b0.x)), __expf(lrelu(a0.y + b0.y)),
                            __expf(lrelu(a0.z + b0.z)), __expf(lrelu(a0.w + b0.w)));
    float4 e1 = make_float4(__expf(lrelu(a1.x + b1.x)), __expf(lrelu(a1.y + b1.y)),
                            __expf(lrelu(a1.z + b1.z)), __expf(lrelu(a1.w + b1.w)));
    atomicAdd(reinterpret_cast<float4*>(g_denom1 + (size_t)d * HEADS), e0);
    atomicAdd(reinterpret_cast<float4*>(g_denom1 + (size_t)d * HEADS + 4), e1);
}

// ---------------- layer 1 edge pass B: weighted aggregation (warp per edge) ----------------
__global__ void edge1_aggregate_kernel() {
    int gw   = (blockIdx.x * blockDim.x + threadIdx.x) >> 5;
    int lane = threadIdx.x & 31;
    if (gw >= N_EDGES) return;
    int s = g_src[gw], d = g_dst[gw];
    int h = lane >> 2;
    float as = __ldg(g_asrc1 + (size_t)s * HEADS + h);
    float ad = __ldg(g_adst1 + (size_t)d * HEADS + h);
    float dn = __ldg(g_denom1 + (size_t)d * HEADS + h);
    float alpha = __expf(lrelu(as + ad)) / (dn + 1e-16f);
    float4 xv = *reinterpret_cast<const float4*>(g_xh1 + (size_t)s * H1 + lane * 4);
    float4 msg = make_float4(xv.x * alpha, xv.y * alpha, xv.z * alpha, xv.w * alpha);
    atomicAdd(reinterpret_cast<float4*>(g_acc1 + (size_t)d * H1 + lane * 4), msg);
}

// ---------------- layer 1 finalize: self-loop msg + bias + ELU ----------------
__global__ void fin1_kernel(const float* __restrict__ b1) {
    int gid = blockIdx.x * blockDim.x + threadIdx.x;
    if (gid >= N_NODES * 32) return;
    int i  = gid >> 5;
    int c4 = gid & 31;
    int h  = c4 >> 2;
    float as = g_asrc1[(size_t)i * HEADS + h];
    float ad = g_adst1[(size_t)i * HEADS + h];
    float al = __expf(lrelu(as + ad)) / (g_denom1[(size_t)i * HEADS + h] + 1e-16f);
    float4 acc = *reinterpret_cast<const float4*>(g_acc1 + (size_t)i * H1 + c4 * 4);
    float4 xv  = *reinterpret_cast<const float4*>(g_xh1 + (size_t)i * H1 + c4 * 4);
    float4 bb  = *reinterpret_cast<const float4*>(b1 + c4 * 4);
    float v;
    v = acc.x + xv.x * al + bb.x; acc.x = v > 0.f ? v : expm1f(v);
    v = acc.y + xv.y * al + bb.y; acc.y = v > 0.f ? v : expm1f(v);
    v = acc.z + xv.z * al + bb.z; acc.z = v > 0.f ? v : expm1f(v);
    v = acc.w + xv.w * al + bb.w; acc.w = v > 0.f ? v : expm1f(v);
    *reinterpret_cast<float4*>(g_acc1 + (size_t)i * H1 + c4 * 4) = acc;
}

// ---------------- layer 2 attention coefficients (warp per node) ----------------
__global__ void attn2_kernel(const float* __restrict__ att_src,
                             const float* __restrict__ att_dst) {
    int gw   = (blockIdx.x * blockDim.x + threadIdx.x) >> 5;
    int lane = threadIdx.x & 31;
    if (gw >= N_NODES) return;
    float2 xv = *reinterpret_cast<const float2*>(g_xh2 + (size_t)gw * OUT_C + lane * 2);
    float2 as = *reinterpret_cast<const float2*>(att_src + lane * 2);
    float2 ad = *reinterpret_cast<const float2*>(att_dst + lane * 2);
    float ps = xv.x * as.x + xv.y * as.y;
    float pd = xv.x * ad.x + xv.y * ad.y;
#pragma unroll
    for (int m = 16; m > 0; m >>= 1) {
        ps += __shfl_xor_sync(0xffffffffu, ps, m);
        pd += __shfl_xor_sync(0xffffffffu, pd, m);
    }
    if (lane == 0) {
        g_asrc2[gw] = ps;
        g_adst2[gw] = pd;
        g_denom2[gw] = __expf(lrelu(ps + pd));   // self-loop seed
    }
}

// ---------------- layer 2 edge pass A ----------------
__global__ void edge2_denom_kernel() {
    int e = blockIdx.x * blockDim.x + threadIdx.x;
    if (e >= N_EDGES) return;
    int s = g_src[e], d = g_dst[e];
    float t = __expf(lrelu(__ldg(g_asrc2 + s) + __ldg(g_adst2 + d)));
    atomicAdd(g_denom2 + d, t);
}

// ---------------- layer 2 edge pass B (warp per edge) ----------------
__global__ void edge2_aggregate_kernel(float* __restrict__ out) {
    int gw   = (blockIdx.x * blockDim.x + threadIdx.x) >> 5;
    int lane = threadIdx.x & 31;
    if (gw >= N_EDGES) return;
    int s = g_src[gw], d = g_dst[gw];
    float as = __ldg(g_asrc2 + s);
    float ad = __ldg(g_adst2 + d);
    float dn = __ldg(g_denom2 + d);
    float alpha = __expf(lrelu(as + ad)) / (dn + 1e-16f);
    float2 xv = *reinterpret_cast<const float2*>(g_xh2 + (size_t)s * OUT_C + lane * 2);
    float2 msg = make_float2(xv.x * alpha, xv.y * alpha);
    atomicAdd(reinterpret_cast<float2*>(out + (size_t)d * OUT_C + lane * 2), msg);
}

// ---------------- layer 2 finalize: self-loop msg + bias ----------------
__global__ void fin2_kernel(const float* __restrict__ b2, float* __restrict__ out) {
    int gid = blockIdx.x * blockDim.x + threadIdx.x;
    if (gid >= N_NODES * 16) return;
    int i = gid >> 4;
    int c = gid & 15;
    float al = __expf(lrelu(g_asrc2[i] + g_adst2[i])) / (g_denom2[i] + 1e-16f);
    float4 o  = *reinterpret_cast<const float4*>(out + (size_t)i * OUT_C + c * 4);
    float4 xv = *reinterpret_cast<const float4*>(g_xh2 + (size_t)i * OUT_C + c * 4);
    float4 bb = *reinterpret_cast<const float4*>(b2 + c * 4);
    o.x += xv.x * al + bb.x;
    o.y += xv.y * al + bb.y;
    o.z += xv.z * al + bb.z;
    o.w += xv.w * al + bb.w;
    *reinterpret_cast<float4*>(out + (size_t)i * OUT_C + c * 4) = o;
}

// ---------------- launch ----------------
extern "C" void kernel_launch(void* const* d_in, const int* in_sizes, int n_in,
                              void* d_out, int out_size) {
    const float* x        = (const float*)d_in[0];
    const int*   ei       = (const int*)d_in[1];
    const float* W1       = (const float*)d_in[2];
    const float* att_src1 = (const float*)d_in[3];
    const float* att_dst1 = (const float*)d_in[4];
    const float* b1       = (const float*)d_in[5];
    const float* W2       = (const float*)d_in[6];
    const float* att_src2 = (const float*)d_in[7];
    const float* att_dst2 = (const float*)d_in[8];
    const float* b2       = (const float*)d_in[9];
    float*       out      = (float*)d_out;

    // CRITICAL: get true DEVICE addresses of the __device__ scratch symbols.
    // Passing the symbol name from host code passes the host shadow address,
    // which GB300's ATS happily (and silently) dereferences into host memory.
    void *p_xh1 = nullptr, *p_acc1 = nullptr, *p_xh2 = nullptr;
    cudaGetSymbolAddress(&p_xh1,  g_xh1);
    cudaGetSymbolAddress(&p_acc1, g_acc1);
    cudaGetSymbolAddress(&p_xh2,  g_xh2);
    float* xh1  = (float*)p_xh1;
    float* acc1 = (float*)p_acc1;
    float* xh2  = (float*)p_xh2;

    const int T = 256;
    const int gemm_blocks  = (N_NODES + 63) / 64;
    const int node_warps   = (N_NODES * 32 + T - 1) / T;
    const int edge_threads = (N_EDGES + T - 1) / T;
    const int edge_warps   = (N_EDGES * 32 + T - 1) / T;

    // ---- canonicalize edge indices (dtype-agnostic) ----
    detect_kernel<<<1, T>>>((const unsigned int*)ei);
    convert_kernel<<<edge_threads, T>>>(ei);

    // ---- layer 1 ----
    zero_acc1_kernel<<<(N_NODES * 32 + T - 1) / T, T>>>();
    gemm_kernel<128, 8><<<gemm_blocks, T>>>(x, W1, xh1, N_NODES);
    attn1_kernel<<<node_warps, T>>>(att_src1, att_dst1);
    edge1_denom_kernel<<<edge_threads, T>>>();
    edge1_aggregate_kernel<<<edge_warps, T>>>();
    fin1_kernel<<<node_warps, T>>>(b1);

    // ---- layer 2 ----
    gemm_kernel<64, 4><<<gemm_blocks, T>>>(acc1, W2, xh2, N_NODES);
    attn2_kernel<<<node_warps, T>>>(att_src2, att_dst2);
    zero_out_kernel<<<(N_NODES * 16 + T - 1) / T, T>>>(out);
    edge2_denom_kernel<<<edge_threads, T>>>();
    edge2_aggregate_kernel<<<edge_warps, T>>>(out);
    fin2_kernel<<<(N_NODES * 16 + T - 1) / T, T>>>(b2, out);
}

// round 12
// speedup vs baseline: 1.0878x; 1.0878x over previous
#include <cuda_runtime.h>
#include <cuda_bf16.h>
#include <cstdint>

// ---------------- problem constants ----------------
#define N_NODES 50000
#define N_EDGES 800000
#define IN_C    128
#define HID_C   16
#define HEADS   8
#define H1      (HEADS * HID_C)   // 128
#define OUT_C   64
#define NEG_SLOPE 0.2f

// ---------------- scratch (device globals; no allocation allowed) ----------------
__device__ float g_xh1[(size_t)N_NODES * H1];
__device__ float g_asrc1[(size_t)N_NODES * HEADS];
__device__ float g_adst1[(size_t)N_NODES * HEADS];
__device__ float g_denom1[(size_t)N_NODES * HEADS];
__device__ float g_acc1[(size_t)N_NODES * H1];
__device__ float g_xh2[(size_t)N_NODES * OUT_C];
__device__ float g_asrc2[N_NODES];
__device__ float g_adst2[N_NODES];
__device__ float g_denom2[N_NODES];
__device__ int   g_src[N_EDGES];
__device__ int   g_dst[N_EDGES];
__device__ int   g_is64;

__device__ __forceinline__ float lrelu(float x) { return x > 0.f ? x : NEG_SLOPE * x; }

// ---------------- edge dtype detection + canonicalization ----------------
__global__ void detect_kernel(const unsigned int* __restrict__ ei32) {
    __shared__ unsigned int sv[256];
    int tid = threadIdx.x;
    unsigned int v = 0;
    for (int i = tid; i < 65536; i += 256) v |= ei32[2 * i + 1];
    sv[tid] = v;
    __syncthreads();
    for (int s = 128; s > 0; s >>= 1) {
        if (tid < s) sv[tid] |= sv[tid + s];
        __syncthreads();
    }
    if (tid == 0) g_is64 = (sv[0] == 0u) ? 1 : 0;
}

__global__ void convert_kernel(const int* __restrict__ ei) {
    int e = blockIdx.x * blockDim.x + threadIdx.x;
    if (e >= N_EDGES) return;
    int s, d;
    if (g_is64) {
        const long long* p = (const long long*)ei;
        s = (int)p[e];
        d = (int)p[N_EDGES + e];
    } else {
        s = ei[e];
        d = ei[e + N_EDGES];
    }
    g_src[e] = s;
    g_dst[e] = d;
}

// ---------------- tiled GEMM: C[M,N] = A[M,128] * B[128,N] ----------------
// BM=128, BK=8, 256 threads. 8x(TN) micro-tile per thread. L1-traffic optimized.
template <int BN, int TN>
__global__ void __launch_bounds__(256, 2)
gemm_kernel(const float* __restrict__ A, const float* __restrict__ B,
            float* __restrict__ C, int M) {
    constexpr int K  = 128;
    constexpr int BM = 128;
    constexpr int BK = 8;
    constexpr int TM = 8;
    __shared__ float As[BK][BM + 4];   // +4 pad keeps 16B alignment, breaks STS conflicts
    __shared__ float Bs[BK][BN];

    int tid = threadIdx.x;
    int tx = tid & 15;        // 16 col-groups
    int ty = tid >> 4;        // 16 row-groups
    int m0 = blockIdx.x * BM;

    float acc[TM][TN];
#pragma unroll
    for (int r = 0; r < TM; r++)
#pragma unroll
        for (int c = 0; c < TN; c++) acc[r][c] = 0.f;

    // A-tile load mapping: 128 rows x 8 cols = 1024 floats, one float4 per thread
    int arow = tid >> 1;            // 0..127
    int acol = (tid & 1) << 2;      // 0 or 4
    // B-tile load mapping: 8 rows x BN cols
    int brow = tid >> 5;            // 0..7
    int bcolf4 = (tid & 31);        // 32 threads per row

    for (int kt = 0; kt < K; kt += BK) {
        float4 a4 = make_float4(0.f, 0.f, 0.f, 0.f);
        int gr = m0 + arow;
        if (gr < M)
            a4 = *reinterpret_cast<const float4*>(A + (size_t)gr * K + kt + acol);
        As[acol + 0][arow] = a4.x;
        As[acol + 1][arow] = a4.y;
        As[acol + 2][arow] = a4.z;
        As[acol + 3][arow] = a4.w;

        if (BN == 128) {
            float4 b4 = *reinterpret_cast<const float4*>(B + (size_t)(kt + brow) * BN + bcolf4 * 4);
            *reinterpret_cast<float4*>(&Bs[brow][bcolf4 * 4]) = b4;
        } else {  // BN == 64
            float2 b2 = *reinterpret_cast<const float2*>(B + (size_t)(kt + brow) * BN + bcolf4 * 2);
            *reinterpret_cast<float2*>(&Bs[brow][bcolf4 * 2]) = b2;
        }
        __syncthreads();

#pragma unroll
        for (int k = 0; k < BK; k++) {
            float a[TM];
            float4 a0 = *reinterpret_cast<const float4*>(&As[k][ty * TM]);
            float4 a1 = *reinterpret_cast<const float4*>(&As[k][ty * TM + 4]);
            a[0] = a0.x; a[1] = a0.y; a[2] = a0.z; a[3] = a0.w;
            a[4] = a1.x; a[5] = a1.y; a[6] = a1.z; a[7] = a1.w;
            float b[TN];
#pragma unroll
            for (int c = 0; c < TN; c += 4) {
                float4 b4 = *reinterpret_cast<const float4*>(&Bs[k][tx * TN + c]);
                b[c] = b4.x; b[c + 1] = b4.y; b[c + 2] = b4.z; b[c + 3] = b4.w;
            }
#pragma unroll
            for (int r = 0; r < TM; r++)
#pragma unroll
                for (int c = 0; c < TN; c++) acc[r][c] += a[r] * b[c];
        }
        __syncthreads();
    }

#pragma unroll
    for (int r = 0; r < TM; r++) {
        int gr = m0 + ty * TM + r;
        if (gr < M) {
#pragma unroll
            for (int c = 0; c < TN; c += 4) {
                float4 v = make_float4(acc[r][c], acc[r][c + 1], acc[r][c + 2], acc[r][c + 3]);
                *reinterpret_cast<float4*>(C + (size_t)gr * BN + tx * TN + c) = v;
            }
        }
    }
}

// ---------------- layer 1 attention coefficients (warp per node) ----------------
__global__ void attn1_kernel(const float* __restrict__ att_src,
                             const float* __restrict__ att_dst) {
    int gw   = (blockIdx.x * blockDim.x + threadIdx.x) >> 5;
    int lane = threadIdx.x & 31;
    if (gw >= N_NODES) return;
    float4 xv = *reinterpret_cast<const float4*>(g_xh1 + (size_t)gw * H1 + lane * 4);
    float4 as = *reinterpret_cast<const float4*>(att_src + lane * 4);
    float4 ad = *reinterpret_cast<const float4*>(att_dst + lane * 4);
    float ps = xv.x * as.x + xv.y * as.y + xv.z * as.z + xv.w * as.w;
    float pd = xv.x * ad.x + xv.y * ad.y + xv.z * ad.z + xv.w * ad.w;
    ps += __shfl_xor_sync(0xffffffffu, ps, 1);
    ps += __shfl_xor_sync(0xffffffffu, ps, 2);
    pd += __shfl_xor_sync(0xffffffffu, pd, 1);
    pd += __shfl_xor_sync(0xffffffffu, pd, 2);
    if ((lane & 3) == 0) {
        int h = lane >> 2;
        g_asrc1[(size_t)gw * HEADS + h] = ps;
        g_adst1[(size_t)gw * HEADS + h] = pd;
        g_denom1[(size_t)gw * HEADS + h] = __expf(lrelu(ps + pd));  // self-loop seed
    }
}

// ---------------- layer 1 fused edge pass: unnormalized numerator + denominator ----------------
__global__ void edge1_aggregate_kernel() {
    int gw   = (blockIdx.x * blockDim.x + threadIdx.x) >> 5;
    int lane = threadIdx.x & 31;
    if (gw >= N_EDGES) return;
    int s = g_src[gw], d = g_dst[gw];
    int h = lane >> 2;
    float as = __ldg(g_asrc1 + (size_t)s * HEADS + h);
    float ad = __ldg(g_adst1 + (size_t)d * HEADS + h);
    float t  = __expf(lrelu(as + ad));       // unnormalized weight
    float4 xv = *reinterpret_cast<const float4*>(g_xh1 + (size_t)s * H1 + lane * 4);
    float4 msg = make_float4(xv.x * t, xv.y * t, xv.z * t, xv.w * t);
    atomicAdd(reinterpret_cast<float4*>(g_acc1 + (size_t)d * H1 + lane * 4), msg);
    if ((lane & 3) == 0)
        atomicAdd(g_denom1 + (size_t)d * HEADS + h, t);
}

// ---------------- layer 1 finalize: normalize + self-loop + bias + ELU ----------------
__global__ void fin1_kernel(const float* __restrict__ b1) {
    int gid = blockIdx.x * blockDim.x + threadIdx.x;
    if (gid >= N_NODES * 32) return;
    int i  = gid >> 5;
    int c4 = gid & 31;
    int h  = c4 >> 2;
    float as = g_asrc1[(size_t)i * HEADS + h];
    float ad = g_adst1[(size_t)i * HEADS + h];
    float ts = __expf(lrelu(as + ad));                         // self-loop weight
    float inv = 1.f / (g_denom1[(size_t)i * HEADS + h] + 1e-16f);
    float4 acc = *reinterpret_cast<const float4*>(g_acc1 + (size_t)i * H1 + c4 * 4);
    float4 xv  = *reinterpret_cast<const float4*>(g_xh1 + (size_t)i * H1 + c4 * 4);
    float4 bb  = *reinterpret_cast<const float4*>(b1 + c4 * 4);
    float v;
    v = (acc.x + xv.x * ts) * inv + bb.x; acc.x = v > 0.f ? v : expm1f(v);
    v = (acc.y + xv.y * ts) * inv + bb.y; acc.y = v > 0.f ? v : expm1f(v);
    v = (acc.z + xv.z * ts) * inv + bb.z; acc.z = v > 0.f ? v : expm1f(v);
    v = (acc.w + xv.w * ts) * inv + bb.w; acc.w = v > 0.f ? v : expm1f(v);
    *reinterpret_cast<float4*>(g_acc1 + (size_t)i * H1 + c4 * 4) = acc;
}

// ---------------- layer 2 attention coefficients (warp per node) ----------------
__global__ void attn2_kernel(const float* __restrict__ att_src,
                             const float* __restrict__ att_dst) {
    int gw   = (blockIdx.x * blockDim.x + threadIdx.x) >> 5;
    int lane = threadIdx.x & 31;
    if (gw >= N_NODES) return;
    float2 xv = *reinterpret_cast<const float2*>(g_xh2 + (size_t)gw * OUT_C + lane * 2);
    float2 as = *reinterpret_cast<const float2*>(att_src + lane * 2);
    float2 ad = *reinterpret_cast<const float2*>(att_dst + lane * 2);
    float ps = xv.x * as.x + xv.y * as.y;
    float pd = xv.x * ad.x + xv.y * ad.y;
#pragma unroll
    for (int m = 16; m > 0; m >>= 1) {
        ps += __shfl_xor_sync(0xffffffffu, ps, m);
        pd += __shfl_xor_sync(0xffffffffu, pd, m);
    }
    if (lane == 0) {
        g_asrc2[gw] = ps;
        g_adst2[gw] = pd;
        g_denom2[gw] = __expf(lrelu(ps + pd));   // self-loop seed
    }
}

// ---------------- layer 2 fused edge pass ----------------
__global__ void edge2_aggregate_kernel(float* __restrict__ out) {
    int gw   = (blockIdx.x * blockDim.x + threadIdx.x) >> 5;
    int lane = threadIdx.x & 31;
    if (gw >= N_EDGES) return;
    int s = g_src[gw], d = g_dst[gw];
    float as = __ldg(g_asrc2 + s);
    float ad = __ldg(g_adst2 + d);
    float t  = __expf(lrelu(as + ad));
    float2 xv = *reinterpret_cast<const float2*>(g_xh2 + (size_t)s * OUT_C + lane * 2);
    float2 msg = make_float2(xv.x * t, xv.y * t);
    atomicAdd(reinterpret_cast<float2*>(out + (size_t)d * OUT_C + lane * 2), msg);
    if (lane == 0)
        atomicAdd(g_denom2 + d, t);
}

// ---------------- layer 2 finalize: normalize + self-loop + bias ----------------
__global__ void fin2_kernel(const float* __restrict__ b2, float* __restrict__ out) {
    int gid = blockIdx.x * blockDim.x + threadIdx.x;
    if (gid >= N_NODES * 16) return;
    int i = gid >> 4;
    int c = gid & 15;
    float ts  = __expf(lrelu(g_asrc2[i] + g_adst2[i]));
    float inv = 1.f / (g_denom2[i] + 1e-16f);
    float4 o  = *reinterpret_cast<const float4*>(out + (size_t)i * OUT_C + c * 4);
    float4 xv = *reinterpret_cast<const float4*>(g_xh2 + (size_t)i * OUT_C + c * 4);
    float4 bb = *reinterpret_cast<const float4*>(b2 + c * 4);
    o.x = (o.x + xv.x * ts) * inv + bb.x;
    o.y = (o.y + xv.y * ts) * inv + bb.y;
    o.z = (o.z + xv.z * ts) * inv + bb.z;
    o.w = (o.w + xv.w * ts) * inv + bb.w;
    *reinterpret_cast<float4*>(out + (size_t)i * OUT_C + c * 4) = o;
}

// ---------------- launch ----------------
extern "C" void kernel_launch(void* const* d_in, const int* in_sizes, int n_in,
                              void* d_out, int out_size) {
    const float* x        = (const float*)d_in[0];
    const int*   ei       = (const int*)d_in[1];
    const float* W1       = (const float*)d_in[2];
    const float* att_src1 = (const float*)d_in[3];
    const float* att_dst1 = (const float*)d_in[4];
    const float* b1       = (const float*)d_in[5];
    const float* W2       = (const float*)d_in[6];
    const float* att_src2 = (const float*)d_in[7];
    const float* att_dst2 = (const float*)d_in[8];
    const float* b2       = (const float*)d_in[9];
    float*       out      = (float*)d_out;

    // True DEVICE addresses of __device__ symbols (host shadow + ATS trap!)
    void *p_xh1 = nullptr, *p_acc1 = nullptr, *p_xh2 = nullptr;
    cudaGetSymbolAddress(&p_xh1,  g_xh1);
    cudaGetSymbolAddress(&p_acc1, g_acc1);
    cudaGetSymbolAddress(&p_xh2,  g_xh2);
    float* xh1  = (float*)p_xh1;
    float* acc1 = (float*)p_acc1;
    float* xh2  = (float*)p_xh2;

    const int T = 256;
    const int gemm_blocks  = (N_NODES + 127) / 128;               // 391
    const int node_warps   = (N_NODES * 32 + T - 1) / T;
    const int edge_threads = (N_EDGES + T - 1) / T;
    const int edge_warps   = (N_EDGES * 32 + T - 1) / T;

    // ---- canonicalize edge indices ----
    detect_kernel<<<1, T>>>((const unsigned int*)ei);
    convert_kernel<<<edge_threads, T>>>(ei);

    // ---- layer 1 ----
    cudaMemsetAsync(acc1, 0, (size_t)N_NODES * H1 * sizeof(float));
    gemm_kernel<128, 8><<<gemm_blocks, T>>>(x, W1, xh1, N_NODES);
    attn1_kernel<<<node_warps, T>>>(att_src1, att_dst1);
    edge1_aggregate_kernel<<<edge_warps, T>>>();
    fin1_kernel<<<node_warps, T>>>(b1);

    // ---- layer 2 ----
    gemm_kernel<64, 4><<<gemm_blocks, T>>>(acc1, W2, xh2, N_NODES);
    attn2_kernel<<<node_warps, T>>>(att_src2, att_dst2);
    cudaMemsetAsync(out, 0, (size_t)N_NODES * OUT_C * sizeof(float));
    edge2_aggregate_kernel<<<edge_warps, T>>>(out);
    fin2_kernel<<<(N_NODES * 16 + T - 1) / T, T>>>(b2, out);
}

// round 13
// speedup vs baseline: 1.3195x; 1.2130x over previous
#include <cuda_runtime.h>
#include <cuda_bf16.h>
#include <cstdint>

// ---------------- problem constants ----------------
#define N_NODES 50000
#define N_EDGES 800000
#define IN_C    128
#define HID_C   16
#define HEADS   8
#define H1      (HEADS * HID_C)   // 128
#define OUT_C   64
#define NEG_SLOPE 0.2f

// ---------------- scratch (device globals) ----------------
__device__ float g_xh1[(size_t)N_NODES * H1];
__device__ float g_asrc1[(size_t)N_NODES * HEADS];
__device__ float g_adst1[(size_t)N_NODES * HEADS];
__device__ float g_acc1[(size_t)N_NODES * H1];
__device__ float g_xh2[(size_t)N_NODES * OUT_C];
__device__ float g_asrc2[N_NODES];
__device__ float g_adst2[N_NODES];
__device__ int   g_src[N_EDGES];
__device__ int   g_dst[N_EDGES];
__device__ int   g_cnt[N_NODES];       // in-degree histogram
__device__ int   g_ptr[N_NODES + 1];   // CSR row pointers (by dst)
__device__ int   g_fill[N_NODES];      // scatter cursors
__device__ int   g_esrc[N_EDGES];      // src indices grouped by dst
__device__ int   g_is64;

__device__ __forceinline__ float lrelu(float x) { return x > 0.f ? x : NEG_SLOPE * x; }

// ---------------- edge dtype detection ----------------
__global__ void detect_kernel(const unsigned int* __restrict__ ei32) {
    __shared__ unsigned int sv[256];
    int tid = threadIdx.x;
    unsigned int v = 0;
    for (int i = tid; i < 65536; i += 256) v |= ei32[2 * i + 1];
    sv[tid] = v;
    __syncthreads();
    for (int s = 128; s > 0; s >>= 1) {
        if (tid < s) sv[tid] |= sv[tid + s];
        __syncthreads();
    }
    if (tid == 0) g_is64 = (sv[0] == 0u) ? 1 : 0;
}

// canonicalize indices + build dst histogram
__global__ void convert_kernel(const int* __restrict__ ei) {
    int e = blockIdx.x * blockDim.x + threadIdx.x;
    if (e >= N_EDGES) return;
    int s, d;
    if (g_is64) {
        const long long* p = (const long long*)ei;
        s = (int)p[e];
        d = (int)p[N_EDGES + e];
    } else {
        s = ei[e];
        d = ei[e + N_EDGES];
    }
    g_src[e] = s;
    g_dst[e] = d;
    atomicAdd(&g_cnt[d], 1);
}

// single-block exclusive scan of g_cnt -> g_ptr, g_fill
#define SCAN_T 1024
#define SCAN_CHUNK ((N_NODES + SCAN_T - 1) / SCAN_T)   // 49
__global__ void scan_kernel() {
    __shared__ int sums[SCAN_T];
    int t = threadIdx.x;
    int base = t * SCAN_CHUNK;
    int s = 0;
    for (int i = 0; i < SCAN_CHUNK; i++) {
        int idx = base + i;
        if (idx < N_NODES) s += g_cnt[idx];
    }
    sums[t] = s;
    __syncthreads();
    // Hillis-Steele inclusive scan over 1024 thread sums
    for (int off = 1; off < SCAN_T; off <<= 1) {
        int v = (t >= off) ? sums[t - off] : 0;
        __syncthreads();
        sums[t] += v;
        __syncthreads();
    }
    int run = sums[t] - s;   // exclusive prefix for this chunk
    for (int i = 0; i < SCAN_CHUNK; i++) {
        int idx = base + i;
        if (idx < N_NODES) {
            g_ptr[idx]  = run;
            g_fill[idx] = run;
            run += g_cnt[idx];
        }
    }
    if (t == SCAN_T - 1) g_ptr[N_NODES] = run;
}

// scatter src indices into dst-grouped buckets
__global__ void scatter_kernel() {
    int e = blockIdx.x * blockDim.x + threadIdx.x;
    if (e >= N_EDGES) return;
    int d = g_dst[e];
    int pos = atomicAdd(&g_fill[d], 1);
    g_esrc[pos] = g_src[e];
}

// ---------------- tiled GEMM: C[M,N] = A[M,128] * B[128,N] ----------------
template <int BN, int TN>
__global__ void __launch_bounds__(256, 2)
gemm_kernel(const float* __restrict__ A, const float* __restrict__ B,
            float* __restrict__ C, int M) {
    constexpr int K  = 128;
    constexpr int BM = 128;
    constexpr int BK = 8;
    constexpr int TM = 8;
    __shared__ float As[BK][BM + 4];
    __shared__ float Bs[BK][BN];

    int tid = threadIdx.x;
    int tx = tid & 15;
    int ty = tid >> 4;
    int m0 = blockIdx.x * BM;

    float acc[TM][TN];
#pragma unroll
    for (int r = 0; r < TM; r++)
#pragma unroll
        for (int c = 0; c < TN; c++) acc[r][c] = 0.f;

    int arow = tid >> 1;
    int acol = (tid & 1) << 2;
    int brow = tid >> 5;
    int bcolf4 = (tid & 31);

    for (int kt = 0; kt < K; kt += BK) {
        float4 a4 = make_float4(0.f, 0.f, 0.f, 0.f);
        int gr = m0 + arow;
        if (gr < M)
            a4 = *reinterpret_cast<const float4*>(A + (size_t)gr * K + kt + acol);
        As[acol + 0][arow] = a4.x;
        As[acol + 1][arow] = a4.y;
        As[acol + 2][arow] = a4.z;
        As[acol + 3][arow] = a4.w;

        if (BN == 128) {
            float4 b4 = *reinterpret_cast<const float4*>(B + (size_t)(kt + brow) * BN + bcolf4 * 4);
            *reinterpret_cast<float4*>(&Bs[brow][bcolf4 * 4]) = b4;
        } else {
            float2 b2 = *reinterpret_cast<const float2*>(B + (size_t)(kt + brow) * BN + bcolf4 * 2);
            *reinterpret_cast<float2*>(&Bs[brow][bcolf4 * 2]) = b2;
        }
        __syncthreads();

#pragma unroll
        for (int k = 0; k < BK; k++) {
            float a[TM];
            float4 a0 = *reinterpret_cast<const float4*>(&As[k][ty * TM]);
            float4 a1 = *reinterpret_cast<const float4*>(&As[k][ty * TM + 4]);
            a[0] = a0.x; a[1] = a0.y; a[2] = a0.z; a[3] = a0.w;
            a[4] = a1.x; a[5] = a1.y; a[6] = a1.z; a[7] = a1.w;
            float b[TN];
#pragma unroll
            for (int c = 0; c < TN; c += 4) {
                float4 b4 = *reinterpret_cast<const float4*>(&Bs[k][tx * TN + c]);
                b[c] = b4.x; b[c + 1] = b4.y; b[c + 2] = b4.z; b[c + 3] = b4.w;
            }
#pragma unroll
            for (int r = 0; r < TM; r++)
#pragma unroll
                for (int c = 0; c < TN; c++) acc[r][c] += a[r] * b[c];
        }
        __syncthreads();
    }

#pragma unroll
    for (int r = 0; r < TM; r++) {
        int gr = m0 + ty * TM + r;
        if (gr < M) {
#pragma unroll
            for (int c = 0; c < TN; c += 4) {
                float4 v = make_float4(acc[r][c], acc[r][c + 1], acc[r][c + 2], acc[r][c + 3]);
                *reinterpret_cast<float4*>(C + (size_t)gr * BN + tx * TN + c) = v;
            }
        }
    }
}

// ---------------- layer 1 attention coefficients (warp per node) ----------------
__global__ void attn1_kernel(const float* __restrict__ att_src,
                             const float* __restrict__ att_dst) {
    int gw   = (blockIdx.x * blockDim.x + threadIdx.x) >> 5;
    int lane = threadIdx.x & 31;
    if (gw >= N_NODES) return;
    float4 xv = *reinterpret_cast<const float4*>(g_xh1 + (size_t)gw * H1 + lane * 4);
    float4 as = *reinterpret_cast<const float4*>(att_src + lane * 4);
    float4 ad = *reinterpret_cast<const float4*>(att_dst + lane * 4);
    float ps = xv.x * as.x + xv.y * as.y + xv.z * as.z + xv.w * as.w;
    float pd = xv.x * ad.x + xv.y * ad.y + xv.z * ad.z + xv.w * ad.w;
    ps += __shfl_xor_sync(0xffffffffu, ps, 1);
    ps += __shfl_xor_sync(0xffffffffu, ps, 2);
    pd += __shfl_xor_sync(0xffffffffu, pd, 1);
    pd += __shfl_xor_sync(0xffffffffu, pd, 2);
    if ((lane & 3) == 0) {
        int h = lane >> 2;
        g_asrc1[(size_t)gw * HEADS + h] = ps;
        g_adst1[(size_t)gw * HEADS + h] = pd;
    }
}

// ---------------- layer 1 CSR aggregation (warp per dst node), fused finalize ----------------
__global__ void aggregate1_kernel(const float* __restrict__ b1) {
    int d    = (blockIdx.x * blockDim.x + threadIdx.x) >> 5;
    int lane = threadIdx.x & 31;
    if (d >= N_NODES) return;
    int h = lane >> 2;

    float adst_h = __ldg(g_adst1 + (size_t)d * HEADS + h);
    float asrc_d = __ldg(g_asrc1 + (size_t)d * HEADS + h);

    // self-loop seed
    float ts = __expf(lrelu(asrc_d + adst_h));
    float4 xd = *reinterpret_cast<const float4*>(g_xh1 + (size_t)d * H1 + lane * 4);
    float4 acc = make_float4(xd.x * ts, xd.y * ts, xd.z * ts, xd.w * ts);
    float den = ts;

    int start = __ldg(g_ptr + d);
    int end   = __ldg(g_ptr + d + 1);

    for (int base = start; base < end; base += 32) {
        int n = end - base; if (n > 32) n = 32;
        int myidx = (base + lane < end) ? g_esrc[base + lane] : 0;
        int j = 0;
        for (; j + 1 < n; j += 2) {
            int s0 = __shfl_sync(0xffffffffu, myidx, j);
            int s1 = __shfl_sync(0xffffffffu, myidx, j + 1);
            float a0 = __ldg(g_asrc1 + (size_t)s0 * HEADS + h);
            float a1 = __ldg(g_asrc1 + (size_t)s1 * HEADS + h);
            float4 x0 = *reinterpret_cast<const float4*>(g_xh1 + (size_t)s0 * H1 + lane * 4);
            float4 x1 = *reinterpret_cast<const float4*>(g_xh1 + (size_t)s1 * H1 + lane * 4);
            float t0 = __expf(lrelu(a0 + adst_h));
            float t1 = __expf(lrelu(a1 + adst_h));
            acc.x += x0.x * t0 + x1.x * t1;
            acc.y += x0.y * t0 + x1.y * t1;
            acc.z += x0.z * t0 + x1.z * t1;
            acc.w += x0.w * t0 + x1.w * t1;
            den += t0 + t1;
        }
        if (j < n) {
            int s0 = __shfl_sync(0xffffffffu, myidx, j);
            float a0 = __ldg(g_asrc1 + (size_t)s0 * HEADS + h);
            float4 x0 = *reinterpret_cast<const float4*>(g_xh1 + (size_t)s0 * H1 + lane * 4);
            float t0 = __expf(lrelu(a0 + adst_h));
            acc.x += x0.x * t0; acc.y += x0.y * t0;
            acc.z += x0.z * t0; acc.w += x0.w * t0;
            den += t0;
        }
    }

    float inv = 1.f / (den + 1e-16f);
    float4 bb = *reinterpret_cast<const float4*>(b1 + lane * 4);
    float v;
    v = acc.x * inv + bb.x; acc.x = v > 0.f ? v : expm1f(v);
    v = acc.y * inv + bb.y; acc.y = v > 0.f ? v : expm1f(v);
    v = acc.z * inv + bb.z; acc.z = v > 0.f ? v : expm1f(v);
    v = acc.w * inv + bb.w; acc.w = v > 0.f ? v : expm1f(v);
    *reinterpret_cast<float4*>(g_acc1 + (size_t)d * H1 + lane * 4) = acc;
}

// ---------------- layer 2 attention coefficients (warp per node) ----------------
__global__ void attn2_kernel(const float* __restrict__ att_src,
                             const float* __restrict__ att_dst) {
    int gw   = (blockIdx.x * blockDim.x + threadIdx.x) >> 5;
    int lane = threadIdx.x & 31;
    if (gw >= N_NODES) return;
    float2 xv = *reinterpret_cast<const float2*>(g_xh2 + (size_t)gw * OUT_C + lane * 2);
    float2 as = *reinterpret_cast<const float2*>(att_src + lane * 2);
    float2 ad = *reinterpret_cast<const float2*>(att_dst + lane * 2);
    float ps = xv.x * as.x + xv.y * as.y;
    float pd = xv.x * ad.x + xv.y * ad.y;
#pragma unroll
    for (int m = 16; m > 0; m >>= 1) {
        ps += __shfl_xor_sync(0xffffffffu, ps, m);
        pd += __shfl_xor_sync(0xffffffffu, pd, m);
    }
    if (lane == 0) {
        g_asrc2[gw] = ps;
        g_adst2[gw] = pd;
    }
}

// ---------------- layer 2 CSR aggregation (warp per dst node), fused finalize ----------------
__global__ void aggregate2_kernel(const float* __restrict__ b2, float* __restrict__ out) {
    int d    = (blockIdx.x * blockDim.x + threadIdx.x) >> 5;
    int lane = threadIdx.x & 31;
    if (d >= N_NODES) return;

    float adst_d = __ldg(g_adst2 + d);
    float asrc_d = __ldg(g_asrc2 + d);

    float ts = __expf(lrelu(asrc_d + adst_d));
    float2 xd = *reinterpret_cast<const float2*>(g_xh2 + (size_t)d * OUT_C + lane * 2);
    float2 acc = make_float2(xd.x * ts, xd.y * ts);
    float den = ts;

    int start = __ldg(g_ptr + d);
    int end   = __ldg(g_ptr + d + 1);

    for (int base = start; base < end; base += 32) {
        int n = end - base; if (n > 32) n = 32;
        int myidx = (base + lane < end) ? g_esrc[base + lane] : 0;
        int j = 0;
        for (; j + 1 < n; j += 2) {
            int s0 = __shfl_sync(0xffffffffu, myidx, j);
            int s1 = __shfl_sync(0xffffffffu, myidx, j + 1);
            float a0 = __ldg(g_asrc2 + s0);
            float a1 = __ldg(g_asrc2 + s1);
            float2 x0 = *reinterpret_cast<const float2*>(g_xh2 + (size_t)s0 * OUT_C + lane * 2);
            float2 x1 = *reinterpret_cast<const float2*>(g_xh2 + (size_t)s1 * OUT_C + lane * 2);
            float t0 = __expf(lrelu(a0 + adst_d));
            float t1 = __expf(lrelu(a1 + adst_d));
            acc.x += x0.x * t0 + x1.x * t1;
            acc.y += x0.y * t0 + x1.y * t1;
            den += t0 + t1;
        }
        if (j < n) {
            int s0 = __shfl_sync(0xffffffffu, myidx, j);
            float a0 = __ldg(g_asrc2 + s0);
            float2 x0 = *reinterpret_cast<const float2*>(g_xh2 + (size_t)s0 * OUT_C + lane * 2);
            float t0 = __expf(lrelu(a0 + adst_d));
            acc.x += x0.x * t0; acc.y += x0.y * t0;
            den += t0;
        }
    }

    float inv = 1.f / (den + 1e-16f);
    float2 bb = *reinterpret_cast<const float2*>(b2 + lane * 2);
    float2 o = make_float2(acc.x * inv + bb.x, acc.y * inv + bb.y);
    *reinterpret_cast<float2*>(out + (size_t)d * OUT_C + lane * 2) = o;
}

// ---------------- launch ----------------
extern "C" void kernel_launch(void* const* d_in, const int* in_sizes, int n_in,
                              void* d_out, int out_size) {
    const float* x        = (const float*)d_in[0];
    const int*   ei       = (const int*)d_in[1];
    const float* W1       = (const float*)d_in[2];
    const float* att_src1 = (const float*)d_in[3];
    const float* att_dst1 = (const float*)d_in[4];
    const float* b1       = (const float*)d_in[5];
    const float* W2       = (const float*)d_in[6];
    const float* att_src2 = (const float*)d_in[7];
    const float* att_dst2 = (const float*)d_in[8];
    const float* b2       = (const float*)d_in[9];
    float*       out      = (float*)d_out;

    // True DEVICE addresses of __device__ symbols (host shadow + ATS trap!)
    void *p_xh1 = nullptr, *p_acc1 = nullptr, *p_xh2 = nullptr, *p_cnt = nullptr;
    cudaGetSymbolAddress(&p_xh1,  g_xh1);
    cudaGetSymbolAddress(&p_acc1, g_acc1);
    cudaGetSymbolAddress(&p_xh2,  g_xh2);
    cudaGetSymbolAddress(&p_cnt,  g_cnt);
    float* xh1  = (float*)p_xh1;
    float* acc1 = (float*)p_acc1;
    float* xh2  = (float*)p_xh2;

    const int T = 256;
    const int gemm_blocks  = (N_NODES + 127) / 128;
    const int node_warps   = (N_NODES * 32 + T - 1) / T;
    const int edge_threads = (N_EDGES + T - 1) / T;

    // ---- CSR build ----
    cudaMemsetAsync(p_cnt, 0, N_NODES * sizeof(int));
    detect_kernel<<<1, T>>>((const unsigned int*)ei);
    convert_kernel<<<edge_threads, T>>>(ei);
    scan_kernel<<<1, SCAN_T>>>();
    scatter_kernel<<<edge_threads, T>>>();

    // ---- layer 1 ----
    gemm_kernel<128, 8><<<gemm_blocks, T>>>(x, W1, xh1, N_NODES);
    attn1_kernel<<<node_warps, T>>>(att_src1, att_dst1);
    aggregate1_kernel<<<node_warps, T>>>(b1);

    // ---- layer 2 ----
    gemm_kernel<64, 4><<<gemm_blocks, T>>>(acc1, W2, xh2, N_NODES);
    attn2_kernel<<<node_warps, T>>>(att_src2, att_dst2);
    aggregate2_kernel<<<node_warps, T>>>(b2, out);
}

// round 14
// speedup vs baseline: 1.3326x; 1.0099x over previous
#include <cuda_runtime.h>
#include <cuda_bf16.h>
#include <cstdint>

// ---------------- problem constants ----------------
#define N_NODES 50000
#define N_EDGES 800000
#define IN_C    128
#define HID_C   16
#define HEADS   8
#define H1      (HEADS * HID_C)   // 128
#define OUT_C   64
#define NEG_SLOPE 0.2f

// ---------------- scratch (device globals) ----------------
__device__ float g_xh1[(size_t)N_NODES * H1];
__device__ float g_asrc1[(size_t)N_NODES * HEADS];
__device__ float g_adst1[(size_t)N_NODES * HEADS];
__device__ float g_acc1[(size_t)N_NODES * H1];
__device__ float g_xh2[(size_t)N_NODES * OUT_C];
__device__ float g_asrc2[N_NODES];
__device__ float g_adst2[N_NODES];
__device__ int   g_src[N_EDGES];
__device__ int   g_dst[N_EDGES];
__device__ int   g_cnt[N_NODES];
__device__ int   g_ptr[N_NODES + 1];
__device__ int   g_fill[N_NODES];
__device__ int   g_esrc[N_EDGES];
__device__ int   g_is64;

__device__ __forceinline__ float lrelu(float x) { return x > 0.f ? x : NEG_SLOPE * x; }

__device__ __forceinline__ unsigned cvt_tf32(float f) {
    unsigned u;
    asm("cvt.rna.tf32.f32 %0, %1;" : "=r"(u) : "f"(f));
    return u;
}
__device__ __forceinline__ void mma_tf32(float d[4], const unsigned a[4], unsigned b0, unsigned b1) {
    asm volatile(
        "mma.sync.aligned.m16n8k8.row.col.f32.tf32.tf32.f32 "
        "{%0,%1,%2,%3},{%4,%5,%6,%7},{%8,%9},{%0,%1,%2,%3};"
        : "+f"(d[0]), "+f"(d[1]), "+f"(d[2]), "+f"(d[3])
        : "r"(a[0]), "r"(a[1]), "r"(a[2]), "r"(a[3]), "r"(b0), "r"(b1));
}

// ---------------- edge dtype detection ----------------
__global__ void detect_kernel(const unsigned int* __restrict__ ei32) {
    __shared__ unsigned int sv[256];
    int tid = threadIdx.x;
    unsigned int v = 0;
    for (int i = tid; i < 65536; i += 256) v |= ei32[2 * i + 1];
    sv[tid] = v;
    __syncthreads();
    for (int s = 128; s > 0; s >>= 1) {
        if (tid < s) sv[tid] |= sv[tid + s];
        __syncthreads();
    }
    if (tid == 0) g_is64 = (sv[0] == 0u) ? 1 : 0;
}

// canonicalize indices + dst histogram, 4 edges/thread for MLP
__global__ void convert_kernel(const int* __restrict__ ei) {
    int e0 = (blockIdx.x * blockDim.x + threadIdx.x) * 4;
    if (e0 >= N_EDGES) return;
    int is64 = g_is64;
    int s[4], d[4];
#pragma unroll
    for (int i = 0; i < 4; i++) {
        int e = e0 + i;
        if (e < N_EDGES) {
            if (is64) {
                const long long* p = (const long long*)ei;
                s[i] = (int)p[e];
                d[i] = (int)p[N_EDGES + e];
            } else {
                s[i] = ei[e];
                d[i] = ei[e + N_EDGES];
            }
        }
    }
#pragma unroll
    for (int i = 0; i < 4; i++) {
        int e = e0 + i;
        if (e < N_EDGES) {
            g_src[e] = s[i];
            g_dst[e] = d[i];
            atomicAdd(&g_cnt[d[i]], 1);
        }
    }
}

// single-block exclusive scan of g_cnt -> g_ptr, g_fill
#define SCAN_T 1024
#define SCAN_CHUNK ((N_NODES + SCAN_T - 1) / SCAN_T)
__global__ void scan_kernel() {
    __shared__ int sums[SCAN_T];
    int t = threadIdx.x;
    int base = t * SCAN_CHUNK;
    int s = 0;
    for (int i = 0; i < SCAN_CHUNK; i++) {
        int idx = base + i;
        if (idx < N_NODES) s += g_cnt[idx];
    }
    sums[t] = s;
    __syncthreads();
    for (int off = 1; off < SCAN_T; off <<= 1) {
        int v = (t >= off) ? sums[t - off] : 0;
        __syncthreads();
        sums[t] += v;
        __syncthreads();
    }
    int run = sums[t] - s;
    for (int i = 0; i < SCAN_CHUNK; i++) {
        int idx = base + i;
        if (idx < N_NODES) {
            g_ptr[idx]  = run;
            g_fill[idx] = run;
            run += g_cnt[idx];
        }
    }
    if (t == SCAN_T - 1) g_ptr[N_NODES] = run;
}

// scatter, 4 edges/thread for MLP
__global__ void scatter_kernel() {
    int e0 = (blockIdx.x * blockDim.x + threadIdx.x) * 4;
    if (e0 >= N_EDGES) return;
    int pos[4], sv[4];
#pragma unroll
    for (int i = 0; i < 4; i++) {
        int e = e0 + i;
        if (e < N_EDGES) {
            sv[i] = g_src[e];
            pos[i] = atomicAdd(&g_fill[g_dst[e]], 1);
        }
    }
#pragma unroll
    for (int i = 0; i < 4; i++) {
        int e = e0 + i;
        if (e < N_EDGES) g_esrc[pos[i]] = sv[i];
    }
}

// ---------------- 3xTF32 tensor-core GEMM: C[M,BN] = A[M,128]*B[128,BN] ----------------
// BM=128, BK=8, 256 threads = 8 warps (4 row x 2 col). Warp tile 32 x BN/2.
template <int BN>
__global__ void __launch_bounds__(256, 2)
gemm_tf32_kernel(const float* __restrict__ A, const float* __restrict__ B,
                 float* __restrict__ C, int M) {
    constexpr int K  = 128;
    constexpr int BM = 128;
    constexpr int BK = 8;
    constexpr int WN = BN / 2;   // warp tile cols
    constexpr int NT = WN / 8;   // n-tiles per warp
    __shared__ float As[BK][BM + 4];
    __shared__ float Bs[BK][BN];

    int tid  = threadIdx.x;
    int lane = tid & 31;
    int wid  = tid >> 5;
    int warpRow = wid & 3;       // 0..3
    int warpCol = wid >> 2;      // 0..1
    int m0 = blockIdx.x * BM;

    int g  = lane >> 2;          // group id 0..7
    int tg = lane & 3;           // thread in group 0..3

    float acc[2][NT][4];
#pragma unroll
    for (int mt = 0; mt < 2; mt++)
#pragma unroll
        for (int nt = 0; nt < NT; nt++)
#pragma unroll
            for (int i = 0; i < 4; i++) acc[mt][nt][i] = 0.f;

    int arow = tid >> 1;
    int acol = (tid & 1) << 2;
    int brow = tid >> 5;
    int bcolf4 = tid & 31;

    for (int kt = 0; kt < K; kt += BK) {
        float4 a4 = make_float4(0.f, 0.f, 0.f, 0.f);
        int gr = m0 + arow;
        if (gr < M)
            a4 = *reinterpret_cast<const float4*>(A + (size_t)gr * K + kt + acol);
        As[acol + 0][arow] = a4.x;
        As[acol + 1][arow] = a4.y;
        As[acol + 2][arow] = a4.z;
        As[acol + 3][arow] = a4.w;

        if (BN == 128) {
            float4 b4 = *reinterpret_cast<const float4*>(B + (size_t)(kt + brow) * BN + bcolf4 * 4);
            *reinterpret_cast<float4*>(&Bs[brow][bcolf4 * 4]) = b4;
        } else {
            float2 b2 = *reinterpret_cast<const float2*>(B + (size_t)(kt + brow) * BN + bcolf4 * 2);
            *reinterpret_cast<float2*>(&Bs[brow][bcolf4 * 2]) = b2;
        }
        __syncthreads();

        // A fragments (hi/lo split), 2 m-tiles
        unsigned ahi[2][4], alo[2][4];
#pragma unroll
        for (int mt = 0; mt < 2; mt++) {
#pragma unroll
            for (int i = 0; i < 4; i++) {
                int row = warpRow * 32 + mt * 16 + g + ((i & 1) ? 8 : 0);
                int col = tg + ((i & 2) ? 4 : 0);
                float av = As[col][row];
                unsigned hi = cvt_tf32(av);
                ahi[mt][i] = hi;
                alo[mt][i] = cvt_tf32(av - __uint_as_float(hi));
            }
        }

#pragma unroll
        for (int nt = 0; nt < NT; nt++) {
            int ncol = warpCol * WN + nt * 8 + g;
            float b0f = Bs[tg][ncol];
            float b1f = Bs[tg + 4][ncol];
            unsigned bhi0 = cvt_tf32(b0f);
            unsigned bhi1 = cvt_tf32(b1f);
            unsigned blo0 = cvt_tf32(b0f - __uint_as_float(bhi0));
            unsigned blo1 = cvt_tf32(b1f - __uint_as_float(bhi1));
#pragma unroll
            for (int mt = 0; mt < 2; mt++) {
                mma_tf32(acc[mt][nt], alo[mt], bhi0, bhi1);   // lo x hi
                mma_tf32(acc[mt][nt], ahi[mt], blo0, blo1);   // hi x lo
                mma_tf32(acc[mt][nt], ahi[mt], bhi0, bhi1);   // hi x hi (last: biggest term)
            }
        }
        __syncthreads();
    }

    // epilogue
#pragma unroll
    for (int mt = 0; mt < 2; mt++) {
        int r1 = m0 + warpRow * 32 + mt * 16 + g;
        int r2 = r1 + 8;
#pragma unroll
        for (int nt = 0; nt < NT; nt++) {
            int cb = warpCol * WN + nt * 8 + tg * 2;
            if (r1 < M)
                *reinterpret_cast<float2*>(C + (size_t)r1 * BN + cb) =
                    make_float2(acc[mt][nt][0], acc[mt][nt][1]);
            if (r2 < M)
                *reinterpret_cast<float2*>(C + (size_t)r2 * BN + cb) =
                    make_float2(acc[mt][nt][2], acc[mt][nt][3]);
        }
    }
}

// ---------------- layer 1 attention coefficients (warp per node) ----------------
__global__ void attn1_kernel(const float* __restrict__ att_src,
                             const float* __restrict__ att_dst) {
    int gw   = (blockIdx.x * blockDim.x + threadIdx.x) >> 5;
    int lane = threadIdx.x & 31;
    if (gw >= N_NODES) return;
    float4 xv = *reinterpret_cast<const float4*>(g_xh1 + (size_t)gw * H1 + lane * 4);
    float4 as = *reinterpret_cast<const float4*>(att_src + lane * 4);
    float4 ad = *reinterpret_cast<const float4*>(att_dst + lane * 4);
    float ps = xv.x * as.x + xv.y * as.y + xv.z * as.z + xv.w * as.w;
    float pd = xv.x * ad.x + xv.y * ad.y + xv.z * ad.z + xv.w * ad.w;
    ps += __shfl_xor_sync(0xffffffffu, ps, 1);
    ps += __shfl_xor_sync(0xffffffffu, ps, 2);
    pd += __shfl_xor_sync(0xffffffffu, pd, 1);
    pd += __shfl_xor_sync(0xffffffffu, pd, 2);
    if ((lane & 3) == 0) {
        int h = lane >> 2;
        g_asrc1[(size_t)gw * HEADS + h] = ps;
        g_adst1[(size_t)gw * HEADS + h] = pd;
    }
}

// ---------------- layer 1 CSR aggregation (warp per dst), fused finalize ----------------
__global__ void aggregate1_kernel(const float* __restrict__ b1) {
    int d    = (blockIdx.x * blockDim.x + threadIdx.x) >> 5;
    int lane = threadIdx.x & 31;
    if (d >= N_NODES) return;
    int h = lane >> 2;

    float adst_h = __ldg(g_adst1 + (size_t)d * HEADS + h);
    float asrc_d = __ldg(g_asrc1 + (size_t)d * HEADS + h);

    float ts = __expf(lrelu(asrc_d + adst_h));
    float4 xd = *reinterpret_cast<const float4*>(g_xh1 + (size_t)d * H1 + lane * 4);
    float4 acc = make_float4(xd.x * ts, xd.y * ts, xd.z * ts, xd.w * ts);
    float den = ts;

    int start = __ldg(g_ptr + d);
    int end   = __ldg(g_ptr + d + 1);

    for (int base = start; base < end; base += 32) {
        int n = end - base; if (n > 32) n = 32;
        int myidx = (base + lane < end) ? g_esrc[base + lane] : 0;
        int j = 0;
        for (; j + 3 < n; j += 4) {
            int s0 = __shfl_sync(0xffffffffu, myidx, j);
            int s1 = __shfl_sync(0xffffffffu, myidx, j + 1);
            int s2 = __shfl_sync(0xffffffffu, myidx, j + 2);
            int s3 = __shfl_sync(0xffffffffu, myidx, j + 3);
            float a0 = __ldg(g_asrc1 + (size_t)s0 * HEADS + h);
            float a1 = __ldg(g_asrc1 + (size_t)s1 * HEADS + h);
            float a2 = __ldg(g_asrc1 + (size_t)s2 * HEADS + h);
            float a3 = __ldg(g_asrc1 + (size_t)s3 * HEADS + h);
            float4 x0 = *reinterpret_cast<const float4*>(g_xh1 + (size_t)s0 * H1 + lane * 4);
            float4 x1 = *reinterpret_cast<const float4*>(g_xh1 + (size_t)s1 * H1 + lane * 4);
            float4 x2 = *reinterpret_cast<const float4*>(g_xh1 + (size_t)s2 * H1 + lane * 4);
            float4 x3 = *reinterpret_cast<const float4*>(g_xh1 + (size_t)s3 * H1 + lane * 4);
            float t0 = __expf(lrelu(a0 + adst_h));
            float t1 = __expf(lrelu(a1 + adst_h));
            float t2 = __expf(lrelu(a2 + adst_h));
            float t3 = __expf(lrelu(a3 + adst_h));
            acc.x += x0.x * t0 + x1.x * t1 + x2.x * t2 + x3.x * t3;
            acc.y += x0.y * t0 + x1.y * t1 + x2.y * t2 + x3.y * t3;
            acc.z += x0.z * t0 + x1.z * t1 + x2.z * t2 + x3.z * t3;
            acc.w += x0.w * t0 + x1.w * t1 + x2.w * t2 + x3.w * t3;
            den += (t0 + t1) + (t2 + t3);
        }
        for (; j < n; j++) {
            int s0 = __shfl_sync(0xffffffffu, myidx, j);
            float a0 = __ldg(g_asrc1 + (size_t)s0 * HEADS + h);
            float4 x0 = *reinterpret_cast<const float4*>(g_xh1 + (size_t)s0 * H1 + lane * 4);
            float t0 = __expf(lrelu(a0 + adst_h));
            acc.x += x0.x * t0; acc.y += x0.y * t0;
            acc.z += x0.z * t0; acc.w += x0.w * t0;
            den += t0;
        }
    }

    float inv = 1.f / (den + 1e-16f);
    float4 bb = *reinterpret_cast<const float4*>(b1 + lane * 4);
    float v;
    v = acc.x * inv + bb.x; acc.x = v > 0.f ? v : expm1f(v);
    v = acc.y * inv + bb.y; acc.y = v > 0.f ? v : expm1f(v);
    v = acc.z * inv + bb.z; acc.z = v > 0.f ? v : expm1f(v);
    v = acc.w * inv + bb.w; acc.w = v > 0.f ? v : expm1f(v);
    *reinterpret_cast<float4*>(g_acc1 + (size_t)d * H1 + lane * 4) = acc;
}

// ---------------- layer 2 attention coefficients (warp per node) ----------------
__global__ void attn2_kernel(const float* __restrict__ att_src,
                             const float* __restrict__ att_dst) {
    int gw   = (blockIdx.x * blockDim.x + threadIdx.x) >> 5;
    int lane = threadIdx.x & 31;
    if (gw >= N_NODES) return;
    float2 xv = *reinterpret_cast<const float2*>(g_xh2 + (size_t)gw * OUT_C + lane * 2);
    float2 as = *reinterpret_cast<const float2*>(att_src + lane * 2);
    float2 ad = *reinterpret_cast<const float2*>(att_dst + lane * 2);
    float ps = xv.x * as.x + xv.y * as.y;
    float pd = xv.x * ad.x + xv.y * ad.y;
#pragma unroll
    for (int m = 16; m > 0; m >>= 1) {
        ps += __shfl_xor_sync(0xffffffffu, ps, m);
        pd += __shfl_xor_sync(0xffffffffu, pd, m);
    }
    if (lane == 0) {
        g_asrc2[gw] = ps;
        g_adst2[gw] = pd;
    }
}

// ---------------- layer 2 CSR aggregation (warp per dst), fused finalize ----------------
__global__ void aggregate2_kernel(const float* __restrict__ b2, float* __restrict__ out) {
    int d    = (blockIdx.x * blockDim.x + threadIdx.x) >> 5;
    int lane = threadIdx.x & 31;
    if (d >= N_NODES) return;

    float adst_d = __ldg(g_adst2 + d);
    float asrc_d = __ldg(g_asrc2 + d);

    float ts = __expf(lrelu(asrc_d + adst_d));
    float2 xd = *reinterpret_cast<const float2*>(g_xh2 + (size_t)d * OUT_C + lane * 2);
    float2 acc = make_float2(xd.x * ts, xd.y * ts);
    float den = ts;

    int start = __ldg(g_ptr + d);
    int end   = __ldg(g_ptr + d + 1);

    for (int base = start; base < end; base += 32) {
        int n = end - base; if (n > 32) n = 32;
        int myidx = (base + lane < end) ? g_esrc[base + lane] : 0;
        int j = 0;
        for (; j + 3 < n; j += 4) {
            int s0 = __shfl_sync(0xffffffffu, myidx, j);
            int s1 = __shfl_sync(0xffffffffu, myidx, j + 1);
            int s2 = __shfl_sync(0xffffffffu, myidx, j + 2);
            int s3 = __shfl_sync(0xffffffffu, myidx, j + 3);
            float a0 = __ldg(g_asrc2 + s0);
            float a1 = __ldg(g_asrc2 + s1);
            float a2 = __ldg(g_asrc2 + s2);
            float a3 = __ldg(g_asrc2 + s3);
            float2 x0 = *reinterpret_cast<const float2*>(g_xh2 + (size_t)s0 * OUT_C + lane * 2);
            float2 x1 = *reinterpret_cast<const float2*>(g_xh2 + (size_t)s1 * OUT_C + lane * 2);
            float2 x2 = *reinterpret_cast<const float2*>(g_xh2 + (size_t)s2 * OUT_C + lane * 2);
            float2 x3 = *reinterpret_cast<const float2*>(g_xh2 + (size_t)s3 * OUT_C + lane * 2);
            float t0 = __expf(lrelu(a0 + adst_d));
            float t1 = __expf(lrelu(a1 + adst_d));
            float t2 = __expf(lrelu(a2 + adst_d));
            float t3 = __expf(lrelu(a3 + adst_d));
            acc.x += x0.x * t0 + x1.x * t1 + x2.x * t2 + x3.x * t3;
            acc.y += x0.y * t0 + x1.y * t1 + x2.y * t2 + x3.y * t3;
            den += (t0 + t1) + (t2 + t3);
        }
        for (; j < n; j++) {
            int s0 = __shfl_sync(0xffffffffu, myidx, j);
            float a0 = __ldg(g_asrc2 + s0);
            float2 x0 = *reinterpret_cast<const float2*>(g_xh2 + (size_t)s0 * OUT_C + lane * 2);
            float t0 = __expf(lrelu(a0 + adst_d));
            acc.x += x0.x * t0; acc.y += x0.y * t0;
            den += t0;
        }
    }

    float inv = 1.f / (den + 1e-16f);
    float2 bb = *reinterpret_cast<const float2*>(b2 + lane * 2);
    float2 o = make_float2(acc.x * inv + bb.x, acc.y * inv + bb.y);
    *reinterpret_cast<float2*>(out + (size_t)d * OUT_C + lane * 2) = o;
}

// ---------------- launch ----------------
extern "C" void kernel_launch(void* const* d_in, const int* in_sizes, int n_in,
                              void* d_out, int out_size) {
    const float* x        = (const float*)d_in[0];
    const int*   ei       = (const int*)d_in[1];
    const float* W1       = (const float*)d_in[2];
    const float* att_src1 = (const float*)d_in[3];
    const float* att_dst1 = (const float*)d_in[4];
    const float* b1       = (const float*)d_in[5];
    const float* W2       = (const float*)d_in[6];
    const float* att_src2 = (const float*)d_in[7];
    const float* att_dst2 = (const float*)d_in[8];
    const float* b2       = (const float*)d_in[9];
    float*       out      = (float*)d_out;

    // True DEVICE addresses of __device__ symbols (host shadow + ATS trap!)
    void *p_xh1 = nullptr, *p_acc1 = nullptr, *p_xh2 = nullptr, *p_cnt = nullptr;
    cudaGetSymbolAddress(&p_xh1,  g_xh1);
    cudaGetSymbolAddress(&p_acc1, g_acc1);
    cudaGetSymbolAddress(&p_xh2,  g_xh2);
    cudaGetSymbolAddress(&p_cnt,  g_cnt);
    float* xh1  = (float*)p_xh1;
    float* acc1 = (float*)p_acc1;
    float* xh2  = (float*)p_xh2;

    const int T = 256;
    const int gemm_blocks  = (N_NODES + 127) / 128;
    const int node_warps   = (N_NODES * 32 + T - 1) / T;
    const int edge4_blocks = (N_EDGES / 4 + T - 1) / T;

    // ---- CSR build ----
    cudaMemsetAsync(p_cnt, 0, N_NODES * sizeof(int));
    detect_kernel<<<1, T>>>((const unsigned int*)ei);
    convert_kernel<<<edge4_blocks, T>>>(ei);
    scan_kernel<<<1, SCAN_T>>>();
    scatter_kernel<<<edge4_blocks, T>>>();

    // ---- layer 1 ----
    gemm_tf32_kernel<128><<<gemm_blocks, T>>>(x, W1, xh1, N_NODES);
    attn1_kernel<<<node_warps, T>>>(att_src1, att_dst1);
    aggregate1_kernel<<<node_warps, T>>>(b1);

    // ---- layer 2 ----
    gemm_tf32_kernel<64><<<gemm_blocks, T>>>(acc1, W2, xh2, N_NODES);
    attn2_kernel<<<node_warps, T>>>(att_src2, att_dst2);
    aggregate2_kernel<<<node_warps, T>>>(b2, out);
}

// round 15
// speedup vs baseline: 1.3337x; 1.0008x over previous
#include <cuda_runtime.h>
#include <cuda_bf16.h>
#include <cstdint>

// ---------------- problem constants ----------------
#define N_NODES 50000
#define N_EDGES 800000
#define IN_C    128
#define HID_C   16
#define HEADS   8
#define H1      (HEADS * HID_C)   // 128
#define OUT_C   64
#define NEG_SLOPE 0.2f

// ---------------- scratch (device globals) ----------------
__device__ float g_xh1[(size_t)N_NODES * H1];
__device__ float g_asrc1[(size_t)N_NODES * HEADS];
__device__ float g_adst1[(size_t)N_NODES * HEADS];
__device__ float g_acc1[(size_t)N_NODES * H1];
__device__ float g_xh2[(size_t)N_NODES * OUT_C];
__device__ float g_asrc2[N_NODES];
__device__ float g_adst2[N_NODES];
__device__ int   g_src[N_EDGES];
__device__ int   g_dst[N_EDGES];
__device__ int   g_cnt[N_NODES];
__device__ int   g_ptr[N_NODES + 1];
__device__ int   g_fill[N_NODES];
__device__ int   g_esrc[N_EDGES];
__device__ int   g_is64;

__device__ __forceinline__ float lrelu(float x) { return x > 0.f ? x : NEG_SLOPE * x; }

__device__ __forceinline__ unsigned cvt_tf32(float f) {
    unsigned u;
    asm("cvt.rna.tf32.f32 %0, %1;" : "=r"(u) : "f"(f));
    return u;
}
__device__ __forceinline__ void mma_tf32(float d[4], const unsigned a[4], unsigned b0, unsigned b1) {
    asm volatile(
        "mma.sync.aligned.m16n8k8.row.col.f32.tf32.tf32.f32 "
        "{%0,%1,%2,%3},{%4,%5,%6,%7},{%8,%9},{%0,%1,%2,%3};"
        : "+f"(d[0]), "+f"(d[1]), "+f"(d[2]), "+f"(d[3])
        : "r"(a[0]), "r"(a[1]), "r"(a[2]), "r"(a[3]), "r"(b0), "r"(b1));
}

// ---------------- edge dtype detection ----------------
__global__ void detect_kernel(const unsigned int* __restrict__ ei32) {
    __shared__ unsigned int sv[256];
    int tid = threadIdx.x;
    unsigned int v = 0;
    for (int i = tid; i < 65536; i += 256) v |= ei32[2 * i + 1];
    sv[tid] = v;
    __syncthreads();
    for (int s = 128; s > 0; s >>= 1) {
        if (tid < s) sv[tid] |= sv[tid + s];
        __syncthreads();
    }
    if (tid == 0) g_is64 = (sv[0] == 0u) ? 1 : 0;
}

// canonicalize indices + dst histogram, 4 edges/thread for MLP
__global__ void convert_kernel(const int* __restrict__ ei) {
    int e0 = (blockIdx.x * blockDim.x + threadIdx.x) * 4;
    if (e0 >= N_EDGES) return;
    int is64 = g_is64;
    int s[4], d[4];
#pragma unroll
    for (int i = 0; i < 4; i++) {
        int e = e0 + i;
        if (e < N_EDGES) {
            if (is64) {
                const long long* p = (const long long*)ei;
                s[i] = (int)p[e];
                d[i] = (int)p[N_EDGES + e];
            } else {
                s[i] = ei[e];
                d[i] = ei[e + N_EDGES];
            }
        }
    }
#pragma unroll
    for (int i = 0; i < 4; i++) {
        int e = e0 + i;
        if (e < N_EDGES) {
            g_src[e] = s[i];
            g_dst[e] = d[i];
            atomicAdd(&g_cnt[d[i]], 1);
        }
    }
}

// single-block exclusive scan of g_cnt -> g_ptr, g_fill
#define SCAN_T 1024
#define SCAN_CHUNK ((N_NODES + SCAN_T - 1) / SCAN_T)
__global__ void scan_kernel() {
    __shared__ int sums[SCAN_T];
    int t = threadIdx.x;
    int base = t * SCAN_CHUNK;
    int s = 0;
    for (int i = 0; i < SCAN_CHUNK; i++) {
        int idx = base + i;
        if (idx < N_NODES) s += g_cnt[idx];
    }
    sums[t] = s;
    __syncthreads();
    for (int off = 1; off < SCAN_T; off <<= 1) {
        int v = (t >= off) ? sums[t - off] : 0;
        __syncthreads();
        sums[t] += v;
        __syncthreads();
    }
    int run = sums[t] - s;
    for (int i = 0; i < SCAN_CHUNK; i++) {
        int idx = base + i;
        if (idx < N_NODES) {
            g_ptr[idx]  = run;
            g_fill[idx] = run;
            run += g_cnt[idx];
        }
    }
    if (t == SCAN_T - 1) g_ptr[N_NODES] = run;
}

// scatter, 4 edges/thread for MLP
__global__ void scatter_kernel() {
    int e0 = (blockIdx.x * blockDim.x + threadIdx.x) * 4;
    if (e0 >= N_EDGES) return;
    int pos[4], sv[4];
#pragma unroll
    for (int i = 0; i < 4; i++) {
        int e = e0 + i;
        if (e < N_EDGES) {
            sv[i] = g_src[e];
            pos[i] = atomicAdd(&g_fill[g_dst[e]], 1);
        }
    }
#pragma unroll
    for (int i = 0; i < 4; i++) {
        int e = e0 + i;
        if (e < N_EDGES) g_esrc[pos[i]] = sv[i];
    }
}

// ---------------- 3xTF32 tensor-core GEMM: C[M,BN] = A[M,128]*B[128,BN] ----------------
// BM=128, BK=8, 256 threads = 8 warps (4 row x 2 col). Warp tile 32 x BN/2.
template <int BN>
__global__ void __launch_bounds__(256, 2)
gemm_tf32_kernel(const float* __restrict__ A, const float* __restrict__ B,
                 float* __restrict__ C, int M) {
    constexpr int K  = 128;
    constexpr int BM = 128;
    constexpr int BK = 8;
    constexpr int WN = BN / 2;   // warp tile cols
    constexpr int NT = WN / 8;   // n-tiles per warp
    __shared__ float As[BK][BM + 4];
    __shared__ float Bs[BK][BN];

    int tid  = threadIdx.x;
    int lane = tid & 31;
    int wid  = tid >> 5;
    int warpRow = wid & 3;       // 0..3
    int warpCol = wid >> 2;      // 0..1
    int m0 = blockIdx.x * BM;

    int g  = lane >> 2;          // group id 0..7
    int tg = lane & 3;           // thread in group 0..3

    float acc[2][NT][4];
#pragma unroll
    for (int mt = 0; mt < 2; mt++)
#pragma unroll
        for (int nt = 0; nt < NT; nt++)
#pragma unroll
            for (int i = 0; i < 4; i++) acc[mt][nt][i] = 0.f;

    int arow = tid >> 1;
    int acol = (tid & 1) << 2;
    int brow = tid >> 5;
    int bcolf4 = tid & 31;

    for (int kt = 0; kt < K; kt += BK) {
        float4 a4 = make_float4(0.f, 0.f, 0.f, 0.f);
        int gr = m0 + arow;
        if (gr < M)
            a4 = *reinterpret_cast<const float4*>(A + (size_t)gr * K + kt + acol);
        As[acol + 0][arow] = a4.x;
        As[acol + 1][arow] = a4.y;
        As[acol + 2][arow] = a4.z;
        As[acol + 3][arow] = a4.w;

        if (BN == 128) {
            float4 b4 = *reinterpret_cast<const float4*>(B + (size_t)(kt + brow) * BN + bcolf4 * 4);
            *reinterpret_cast<float4*>(&Bs[brow][bcolf4 * 4]) = b4;
        } else {
            float2 b2 = *reinterpret_cast<const float2*>(B + (size_t)(kt + brow) * BN + bcolf4 * 2);
            *reinterpret_cast<float2*>(&Bs[brow][bcolf4 * 2]) = b2;
        }
        __syncthreads();

        // A fragments (hi/lo split), 2 m-tiles
        unsigned ahi[2][4], alo[2][4];
#pragma unroll
        for (int mt = 0; mt < 2; mt++) {
#pragma unroll
            for (int i = 0; i < 4; i++) {
                int row = warpRow * 32 + mt * 16 + g + ((i & 1) ? 8 : 0);
                int col = tg + ((i & 2) ? 4 : 0);
                float av = As[col][row];
                unsigned hi = cvt_tf32(av);
                ahi[mt][i] = hi;
                alo[mt][i] = cvt_tf32(av - __uint_as_float(hi));
            }
        }

#pragma unroll
        for (int nt = 0; nt < NT; nt++) {
            int ncol = warpCol * WN + nt * 8 + g;
            float b0f = Bs[tg][ncol];
            float b1f = Bs[tg + 4][ncol];
            unsigned bhi0 = cvt_tf32(b0f);
            unsigned bhi1 = cvt_tf32(b1f);
            unsigned blo0 = cvt_tf32(b0f - __uint_as_float(bhi0));
            unsigned blo1 = cvt_tf32(b1f - __uint_as_float(bhi1));
#pragma unroll
            for (int mt = 0; mt < 2; mt++) {
                mma_tf32(acc[mt][nt], alo[mt], bhi0, bhi1);   // lo x hi
                mma_tf32(acc[mt][nt], ahi[mt], blo0, blo1);   // hi x lo
                mma_tf32(acc[mt][nt], ahi[mt], bhi0, bhi1);   // hi x hi (last: biggest term)
            }
        }
        __syncthreads();
    }

    // epilogue
#pragma unroll
    for (int mt = 0; mt < 2; mt++) {
        int r1 = m0 + warpRow * 32 + mt * 16 + g;
        int r2 = r1 + 8;
#pragma unroll
        for (int nt = 0; nt < NT; nt++) {
            int cb = warpCol * WN + nt * 8 + tg * 2;
            if (r1 < M)
                *reinterpret_cast<float2*>(C + (size_t)r1 * BN + cb) =
                    make_float2(acc[mt][nt][0], acc[mt][nt][1]);
            if (r2 < M)
                *reinterpret_cast<float2*>(C + (size_t)r2 * BN + cb) =
                    make_float2(acc[mt][nt][2], acc[mt][nt][3]);
        }
    }
}

// ---------------- layer 1 attention coefficients (warp per node) ----------------
__global__ void attn1_kernel(const float* __restrict__ att_src,
                             const float* __restrict__ att_dst) {
    int gw   = (blockIdx.x * blockDim.x + threadIdx.x) >> 5;
    int lane = threadIdx.x & 31;
    if (gw >= N_NODES) return;
    float4 xv = *reinterpret_cast<const float4*>(g_xh1 + (size_t)gw * H1 + lane * 4);
    float4 as = *reinterpret_cast<const float4*>(att_src + lane * 4);
    float4 ad = *reinterpret_cast<const float4*>(att_dst + lane * 4);
    float ps = xv.x * as.x + xv.y * as.y + xv.z * as.z + xv.w * as.w;
    float pd = xv.x * ad.x + xv.y * ad.y + xv.z * ad.z + xv.w * ad.w;
    ps += __shfl_xor_sync(0xffffffffu, ps, 1);
    ps += __shfl_xor_sync(0xffffffffu, ps, 2);
    pd += __shfl_xor_sync(0xffffffffu, pd, 1);
    pd += __shfl_xor_sync(0xffffffffu, pd, 2);
    if ((lane & 3) == 0) {
        int h = lane >> 2;
        g_asrc1[(size_t)gw * HEADS + h] = ps;
        g_adst1[(size_t)gw * HEADS + h] = pd;
    }
}

// ---------------- layer 1 CSR aggregation (warp per dst), fused finalize ----------------
__global__ void aggregate1_kernel(const float* __restrict__ b1) {
    int d    = (blockIdx.x * blockDim.x + threadIdx.x) >> 5;
    int lane = threadIdx.x & 31;
    if (d >= N_NODES) return;
    int h = lane >> 2;

    float adst_h = __ldg(g_adst1 + (size_t)d * HEADS + h);
    float asrc_d = __ldg(g_asrc1 + (size_t)d * HEADS + h);

    float ts = __expf(lrelu(asrc_d + adst_h));
    float4 xd = *reinterpret_cast<const float4*>(g_xh1 + (size_t)d * H1 + lane * 4);
    float4 acc = make_float4(xd.x * ts, xd.y * ts, xd.z * ts, xd.w * ts);
    float den = ts;

    int start = __ldg(g_ptr + d);
    int end   = __ldg(g_ptr + d + 1);

    for (int base = start; base < end; base += 32) {
        int n = end - base; if (n > 32) n = 32;
        int myidx = (base + lane < end) ? g_esrc[base + lane] : 0;
        int j = 0;
        for (; j + 3 < n; j += 4) {
            int s0 = __shfl_sync(0xffffffffu, myidx, j);
            int s1 = __shfl_sync(0xffffffffu, myidx, j + 1);
            int s2 = __shfl_sync(0xffffffffu, myidx, j + 2);
            int s3 = __shfl_sync(0xffffffffu, myidx, j + 3);
            float a0 = __ldg(g_asrc1 + (size_t)s0 * HEADS + h);
            float a1 = __ldg(g_asrc1 + (size_t)s1 * HEADS + h);
            float a2 = __ldg(g_asrc1 + (size_t)s2 * HEADS + h);
            float a3 = __ldg(g_asrc1 + (size_t)s3 * HEADS + h);
            float4 x0 = *reinterpret_cast<const float4*>(g_xh1 + (size_t)s0 * H1 + lane * 4);
            float4 x1 = *reinterpret_cast<const float4*>(g_xh1 + (size_t)s1 * H1 + lane * 4);
            float4 x2 = *reinterpret_cast<const float4*>(g_xh1 + (size_t)s2 * H1 + lane * 4);
            float4 x3 = *reinterpret_cast<const float4*>(g_xh1 + (size_t)s3 * H1 + lane * 4);
            float t0 = __expf(lrelu(a0 + adst_h));
            float t1 = __expf(lrelu(a1 + adst_h));
            float t2 = __expf(lrelu(a2 + adst_h));
            float t3 = __expf(lrelu(a3 + adst_h));
            acc.x += x0.x * t0 + x1.x * t1 + x2.x * t2 + x3.x * t3;
            acc.y += x0.y * t0 + x1.y * t1 + x2.y * t2 + x3.y * t3;
            acc.z += x0.z * t0 + x1.z * t1 + x2.z * t2 + x3.z * t3;
            acc.w += x0.w * t0 + x1.w * t1 + x2.w * t2 + x3.w * t3;
            den += (t0 + t1) + (t2 + t3);
        }
        for (; j < n; j++) {
            int s0 = __shfl_sync(0xffffffffu, myidx, j);
            float a0 = __ldg(g_asrc1 + (size_t)s0 * HEADS + h);
            float4 x0 = *reinterpret_cast<const float4*>(g_xh1 + (size_t)s0 * H1 + lane * 4);
            float t0 = __expf(lrelu(a0 + adst_h));
            acc.x += x0.x * t0; acc.y += x0.y * t0;
            acc.z += x0.z * t0; acc.w += x0.w * t0;
            den += t0;
        }
    }

    float inv = 1.f / (den + 1e-16f);
    float4 bb = *reinterpret_cast<const float4*>(b1 + lane * 4);
    float v;
    v = acc.x * inv + bb.x; acc.x = v > 0.f ? v : expm1f(v);
    v = acc.y * inv + bb.y; acc.y = v > 0.f ? v : expm1f(v);
    v = acc.z * inv + bb.z; acc.z = v > 0.f ? v : expm1f(v);
    v = acc.w * inv + bb.w; acc.w = v > 0.f ? v : expm1f(v);
    *reinterpret_cast<float4*>(g_acc1 + (size_t)d * H1 + lane * 4) = acc;
}

// ---------------- layer 2 attention coefficients (warp per node) ----------------
__global__ void attn2_kernel(const float* __restrict__ att_src,
                             const float* __restrict__ att_dst) {
    int gw   = (blockIdx.x * blockDim.x + threadIdx.x) >> 5;
    int lane = threadIdx.x & 31;
    if (gw >= N_NODES) return;
    float2 xv = *reinterpret_cast<const float2*>(g_xh2 + (size_t)gw * OUT_C + lane * 2);
    float2 as = *reinterpret_cast<const float2*>(att_src + lane * 2);
    float2 ad = *reinterpret_cast<const float2*>(att_dst + lane * 2);
    float ps = xv.x * as.x + xv.y * as.y;
    float pd = xv.x * ad.x + xv.y * ad.y;
#pragma unroll
    for (int m = 16; m > 0; m >>= 1) {
        ps += __shfl_xor_sync(0xffffffffu, ps, m);
        pd += __shfl_xor_sync(0xffffffffu, pd, m);
    }
    if (lane == 0) {
        g_asrc2[gw] = ps;
        g_adst2[gw] = pd;
    }
}

// ---------------- layer 2 CSR aggregation (warp per dst), fused finalize ----------------
__global__ void aggregate2_kernel(const float* __restrict__ b2, float* __restrict__ out) {
    int d    = (blockIdx.x * blockDim.x + threadIdx.x) >> 5;
    int lane = threadIdx.x & 31;
    if (d >= N_NODES) return;

    float adst_d = __ldg(g_adst2 + d);
    float asrc_d = __ldg(g_asrc2 + d);

    float ts = __expf(lrelu(asrc_d + adst_d));
    float2 xd = *reinterpret_cast<const float2*>(g_xh2 + (size_t)d * OUT_C + lane * 2);
    float2 acc = make_float2(xd.x * ts, xd.y * ts);
    float den = ts;

    int start = __ldg(g_ptr + d);
    int end   = __ldg(g_ptr + d + 1);

    for (int base = start; base < end; base += 32) {
        int n = end - base; if (n > 32) n = 32;
        int myidx = (base + lane < end) ? g_esrc[base + lane] : 0;
        int j = 0;
        for (; j + 3 < n; j += 4) {
            int s0 = __shfl_sync(0xffffffffu, myidx, j);
            int s1 = __shfl_sync(0xffffffffu, myidx, j + 1);
            int s2 = __shfl_sync(0xffffffffu, myidx, j + 2);
            int s3 = __shfl_sync(0xffffffffu, myidx, j + 3);
            float a0 = __ldg(g_asrc2 + s0);
            float a1 = __ldg(g_asrc2 + s1);
            float a2 = __ldg(g_asrc2 + s2);
            float a3 = __ldg(g_asrc2 + s3);
            float2 x0 = *reinterpret_cast<const float2*>(g_xh2 + (size_t)s0 * OUT_C + lane * 2);
            float2 x1 = *reinterpret_cast<const float2*>(g_xh2 + (size_t)s1 * OUT_C + lane * 2);
            float2 x2 = *reinterpret_cast<const float2*>(g_xh2 + (size_t)s2 * OUT_C + lane * 2);
            float2 x3 = *reinterpret_cast<const float2*>(g_xh2 + (size_t)s3 * OUT_C + lane * 2);
            float t0 = __expf(lrelu(a0 + adst_d));
            float t1 = __expf(lrelu(a1 + adst_d));
            float t2 = __expf(lrelu(a2 + adst_d));
            float t3 = __expf(lrelu(a3 + adst_d));
            acc.x += x0.x * t0 + x1.x * t1 + x2.x * t2 + x3.x * t3;
            acc.y += x0.y * t0 + x1.y * t1 + x2.y * t2 + x3.y * t3;
            den += (t0 + t1) + (t2 + t3);
        }
        for (; j < n; j++) {
            int s0 = __shfl_sync(0xffffffffu, myidx, j);
            float a0 = __ldg(g_asrc2 + s0);
            float2 x0 = *reinterpret_cast<const float2*>(g_xh2 + (size_t)s0 * OUT_C + lane * 2);
            float t0 = __expf(lrelu(a0 + adst_d));
            acc.x += x0.x * t0; acc.y += x0.y * t0;
            den += t0;
        }
    }

    float inv = 1.f / (den + 1e-16f);
    float2 bb = *reinterpret_cast<const float2*>(b2 + lane * 2);
    float2 o = make_float2(acc.x * inv + bb.x, acc.y * inv + bb.y);
    *reinterpret_cast<float2*>(out + (size_t)d * OUT_C + lane * 2) = o;
}

// ---------------- launch ----------------
extern "C" void kernel_launch(void* const* d_in, const int* in_sizes, int n_in,
                              void* d_out, int out_size) {
    const float* x        = (const float*)d_in[0];
    const int*   ei       = (const int*)d_in[1];
    const float* W1       = (const float*)d_in[2];
    const float* att_src1 = (const float*)d_in[3];
    const float* att_dst1 = (const float*)d_in[4];
    const float* b1       = (const float*)d_in[5];
    const float* W2       = (const float*)d_in[6];
    const float* att_src2 = (const float*)d_in[7];
    const float* att_dst2 = (const float*)d_in[8];
    const float* b2       = (const float*)d_in[9];
    float*       out      = (float*)d_out;

    // True DEVICE addresses of __device__ symbols (host shadow + ATS trap!)
    void *p_xh1 = nullptr, *p_acc1 = nullptr, *p_xh2 = nullptr, *p_cnt = nullptr;
    cudaGetSymbolAddress(&p_xh1,  g_xh1);
    cudaGetSymbolAddress(&p_acc1, g_acc1);
    cudaGetSymbolAddress(&p_xh2,  g_xh2);
    cudaGetSymbolAddress(&p_cnt,  g_cnt);
    float* xh1  = (float*)p_xh1;
    float* acc1 = (float*)p_acc1;
    float* xh2  = (float*)p_xh2;

    const int T = 256;
    const int gemm_blocks  = (N_NODES + 127) / 128;
    const int node_warps   = (N_NODES * 32 + T - 1) / T;
    const int edge4_blocks = (N_EDGES / 4 + T - 1) / T;

    // ---- CSR build ----
    cudaMemsetAsync(p_cnt, 0, N_NODES * sizeof(int));
    detect_kernel<<<1, T>>>((const unsigned int*)ei);
    convert_kernel<<<edge4_blocks, T>>>(ei);
    scan_kernel<<<1, SCAN_T>>>();
    scatter_kernel<<<edge4_blocks, T>>>();

    // ---- layer 1 ----
    gemm_tf32_kernel<128><<<gemm_blocks, T>>>(x, W1, xh1, N_NODES);
    attn1_kernel<<<node_warps, T>>>(att_src1, att_dst1);
    aggregate1_kernel<<<node_warps, T>>>(b1);

    // ---- layer 2 ----
    gemm_tf32_kernel<64><<<gemm_blocks, T>>>(acc1, W2, xh2, N_NODES);
    attn2_kernel<<<node_warps, T>>>(att_src2, att_dst2);
    aggregate2_kernel<<<node_warps, T>>>(b2, out);
}